// round 7
// baseline (speedup 1.0000x reference)
#include <cuda_runtime.h>
#include <cuda_fp16.h>

// LightGCN pull-form: out = 0.25*(x0+x1+x2+x3), x_{l+1}[c] = sum_{e: col[e]=c} norm_e * x_l[row[e]]
// norm_e = rsqrt(deg[row])*rsqrt(deg[col]); deg = in-degree over col (symmetric list).
// edge_index int32. CSR (src-only) rebuilt every call; fp16 feature storage, fp32 math.
// Pull: one warp per dst node, QUARTER-warp per edge (4 edges in flight), 32B lane slices.
// Final mean fused into the 3rd pull.

static constexpr int    NU = 100000;
static constexpr int    NI = 50000;
static constexpr int    NN = NU + NI;        // 150000
static constexpr int    D  = 128;
static constexpr int    NE = 2000000;
static constexpr size_t ND = (size_t)NN * D; // 19.2M elems

static constexpr int SCAN_B   = 1024;
static constexpr int NSCANBLK = (NN + SCAN_B - 1) / SCAN_B;  // 147
static_assert(NSCANBLK <= 256, "scan2 single block assumption");

// ---- static scratch ----
__device__ __half g_xh[3][ND];    // x0h, x1h, x2h fp16 features (38.4 MB each)
__device__ float  g_dinv[NN];
__device__ int    g_deg[NN];
__device__ int    g_rowptr[NN + 1];
__device__ int    g_cursor[NN];
__device__ int    g_bsum[256];
__device__ int    g_edge[NE];     // src only, grouped by dst

// ---- helpers ----
__device__ __forceinline__ float4 h4_to_f4(uint2 v) {
    float2 f0 = __half22float2(*reinterpret_cast<__half2*>(&v.x));
    float2 f1 = __half22float2(*reinterpret_cast<__half2*>(&v.y));
    return make_float4(f0.x, f0.y, f1.x, f1.y);
}
__device__ __forceinline__ uint2 f4_to_h4(float4 v) {
    __half2 h0 = __floats2half2_rn(v.x, v.y);
    __half2 h1 = __floats2half2_rn(v.z, v.w);
    uint2 o;
    o.x = *reinterpret_cast<unsigned*>(&h0);
    o.y = *reinterpret_cast<unsigned*>(&h1);
    return o;
}

// ---------------- degree ----------------
__global__ void deg_kernel(const int* __restrict__ col, int E) {
    int e = blockIdx.x * blockDim.x + threadIdx.x;
    if (e < E) {
        unsigned c = (unsigned)col[e];
        if (c < (unsigned)NN) atomicAdd(&g_deg[c], 1);
    }
}

// ---------------- scan part 1 (+ fused dinv) ----------------
__global__ void scan1_kernel() {
    __shared__ int s[SCAN_B];
    int tid = threadIdx.x;
    int i = blockIdx.x * SCAN_B + tid;
    int v = (i < NN) ? g_deg[i] : 0;
    if (i < NN) g_dinv[i] = (v > 0) ? rsqrtf((float)v) : 0.0f;
    s[tid] = v;
    __syncthreads();
    for (int off = 1; off < SCAN_B; off <<= 1) {
        int t = (tid >= off) ? s[tid - off] : 0;
        __syncthreads();
        s[tid] += t;
        __syncthreads();
    }
    if (i < NN) g_rowptr[i] = s[tid] - v;
    if (tid == SCAN_B - 1) g_bsum[blockIdx.x] = s[tid];
}

__global__ void scan2_kernel() {
    __shared__ int s[256];
    int tid = threadIdx.x;
    int v = (tid < NSCANBLK) ? g_bsum[tid] : 0;
    s[tid] = v;
    __syncthreads();
    for (int off = 1; off < 256; off <<= 1) {
        int t = (tid >= off) ? s[tid - off] : 0;
        __syncthreads();
        s[tid] += t;
        __syncthreads();
    }
    g_bsum[tid] = s[tid] - v;
}

__global__ void scan3_kernel(int E) {
    int i = blockIdx.x * blockDim.x + threadIdx.x;
    if (i < NN) {
        int rp = g_rowptr[i] + g_bsum[i / SCAN_B];
        g_rowptr[i] = rp;
        g_cursor[i] = rp;
    }
    if (i == 0) g_rowptr[NN] = E;
}

// ---------------- CSR fill (src only) ----------------
__global__ void fill_kernel(const int* __restrict__ row,
                            const int* __restrict__ col, int E) {
    int e = blockIdx.x * blockDim.x + threadIdx.x;
    if (e < E) {
        unsigned r = (unsigned)row[e];
        unsigned c = (unsigned)col[e];
        if (r < (unsigned)NN && c < (unsigned)NN) {
            int pos = atomicAdd(&g_cursor[c], 1);
            g_edge[pos] = (int)r;
        }
    }
}

// ---------------- x0h = fp16(concat(user, item)) ----------------
__global__ void cvt0_kernel(const float* __restrict__ user_w,
                            const float* __restrict__ item_w) {
    size_t i = (size_t)blockIdx.x * blockDim.x + threadIdx.x; // float4 index
    const size_t n4  = ND / 4;
    const size_t nu4 = (size_t)NU * (D / 4);
    if (i < n4) {
        float4 v = (i < nu4) ? ((const float4*)user_w)[i]
                             : ((const float4*)item_w)[i - nu4];
        ((uint2*)g_xh[0])[i] = f4_to_h4(v);
    }
}

// ---------------- pull ----------------
// One warp per dst node; quarter-warp per edge; lane slice = 32 B (2 x uint4 = 16 halves).
// quarter = lane>>3 picks the edge within a group of 4; sub = lane&7 picks the slice.
// FINAL: instead of storing fp16 x3, emit out = 0.25*(x0_fp32 + x1h + x2h + x3_fp32).
template <bool FINAL>
__global__ void __launch_bounds__(256) pull_kernel(
    int lin, int lout,
    const float* __restrict__ user_w, const float* __restrict__ item_w,
    float* __restrict__ out)
{
    int node = (int)((blockIdx.x * (size_t)blockDim.x + threadIdx.x) >> 5);
    int lane = threadIdx.x & 31;
    if (node >= NN) return;

    int beg = g_rowptr[node];
    int end = g_rowptr[node + 1];
    float dn = g_dinv[node];

    int quarter = lane >> 3;  // 0..3: edge within group
    int sub     = lane & 7;   // 0..7: 32B slice within 256B row

    const uint4* __restrict__ xin = (const uint4*)g_xh[lin]; // 16 uint4 per row

    float a0=0.f,a1=0.f,a2=0.f,a3=0.f,a4=0.f,a5=0.f,a6=0.f,a7=0.f;
    float a8=0.f,a9=0.f,a10=0.f,a11=0.f,a12=0.f,a13=0.f,a14=0.f,a15=0.f;

    for (int j = beg; j < end; j += 4) {
        int jj = j + quarter;
        float nrm = 0.f;
        uint4 r0 = make_uint4(0u,0u,0u,0u);
        uint4 r1 = make_uint4(0u,0u,0u,0u);
        if (jj < end) {
            int src = g_edge[jj];
            nrm = g_dinv[src] * dn;
            const uint4* p = xin + (size_t)src * 16 + sub * 2;
            r0 = p[0];
            r1 = p[1];
        }
        float2 f;
        f = __half22float2(*reinterpret_cast<__half2*>(&r0.x)); a0  = fmaf(nrm, f.x, a0);  a1  = fmaf(nrm, f.y, a1);
        f = __half22float2(*reinterpret_cast<__half2*>(&r0.y)); a2  = fmaf(nrm, f.x, a2);  a3  = fmaf(nrm, f.y, a3);
        f = __half22float2(*reinterpret_cast<__half2*>(&r0.z)); a4  = fmaf(nrm, f.x, a4);  a5  = fmaf(nrm, f.y, a5);
        f = __half22float2(*reinterpret_cast<__half2*>(&r0.w)); a6  = fmaf(nrm, f.x, a6);  a7  = fmaf(nrm, f.y, a7);
        f = __half22float2(*reinterpret_cast<__half2*>(&r1.x)); a8  = fmaf(nrm, f.x, a8);  a9  = fmaf(nrm, f.y, a9);
        f = __half22float2(*reinterpret_cast<__half2*>(&r1.y)); a10 = fmaf(nrm, f.x, a10); a11 = fmaf(nrm, f.y, a11);
        f = __half22float2(*reinterpret_cast<__half2*>(&r1.z)); a12 = fmaf(nrm, f.x, a12); a13 = fmaf(nrm, f.y, a13);
        f = __half22float2(*reinterpret_cast<__half2*>(&r1.w)); a14 = fmaf(nrm, f.x, a14); a15 = fmaf(nrm, f.y, a15);
    }

    // combine the 4 quarters (xor 8 then xor 16)
    #define RED(v) v += __shfl_xor_sync(0xFFFFFFFFu, v, 8); v += __shfl_xor_sync(0xFFFFFFFFu, v, 16);
    RED(a0) RED(a1) RED(a2) RED(a3) RED(a4) RED(a5) RED(a6) RED(a7)
    RED(a8) RED(a9) RED(a10) RED(a11) RED(a12) RED(a13) RED(a14) RED(a15)
    #undef RED

    // Each lane now holds the full 16-wide slice sum for its sub.
    // Distribute the writeback: lane (quarter,sub) handles features sub*16 + quarter*4 .. +3.
    float b0, b1, b2, b3;
    if      (quarter == 0) { b0 = a0;  b1 = a1;  b2 = a2;  b3 = a3;  }
    else if (quarter == 1) { b0 = a4;  b1 = a5;  b2 = a6;  b3 = a7;  }
    else if (quarter == 2) { b0 = a8;  b1 = a9;  b2 = a10; b3 = a11; }
    else                   { b0 = a12; b1 = a13; b2 = a14; b3 = a15; }

    size_t idx = (size_t)node * 32 + sub * 4 + quarter;  // float4 / uint2 granule index

    if (FINAL) {
        float4 x0 = (node < NU)
            ? ((const float4*)user_w)[(size_t)node * 32 + sub * 4 + quarter]
            : ((const float4*)item_w)[(size_t)(node - NU) * 32 + sub * 4 + quarter];
        float4 x1 = h4_to_f4(((const uint2*)g_xh[1])[idx]);
        float4 x2 = h4_to_f4(((const uint2*)g_xh[2])[idx]);
        float4 o;
        o.x = 0.25f * (x0.x + x1.x + x2.x + b0);
        o.y = 0.25f * (x0.y + x1.y + x2.y + b1);
        o.z = 0.25f * (x0.z + x1.z + x2.z + b2);
        o.w = 0.25f * (x0.w + x1.w + x2.w + b3);
        ((float4*)out)[idx] = o;
    } else {
        ((uint2*)g_xh[lout])[idx] = f4_to_h4(make_float4(b0, b1, b2, b3));
    }
}

extern "C" void kernel_launch(void* const* d_in, const int* in_sizes, int n_in,
                              void* d_out, int out_size)
{
    const int*   edge_index = (const int*)d_in[0];   // [2, E] int32
    const float* user_w     = (const float*)d_in[1]; // [NU, D]
    const float* item_w     = (const float*)d_in[2]; // [NI, D]
    float*       out        = (float*)d_out;         // [NN, D]

    const int E = in_sizes[0] / 2;
    const int* row = edge_index;
    const int* col = edge_index + E;

    const int TB = 256;
    const int n4_blocks = (int)((ND / 4 + TB - 1) / TB);
    const int nn_blocks = (NN + TB - 1) / TB;
    const int e_blocks  = (E + TB - 1) / TB;
    const int pw_blocks = (NN + (TB / 32) - 1) / (TB / 32);

    // zero degree via captured memset
    void* deg_ptr = nullptr;
    cudaGetSymbolAddress(&deg_ptr, g_deg);
    cudaMemsetAsync(deg_ptr, 0, NN * sizeof(int));

    // degree -> (scan + dinv) -> rowptr -> fill
    deg_kernel<<<e_blocks, TB>>>(col, E);
    scan1_kernel<<<NSCANBLK, SCAN_B>>>();
    scan2_kernel<<<1, 256>>>();
    scan3_kernel<<<nn_blocks, TB>>>(E);
    fill_kernel<<<e_blocks, TB>>>(row, col, E);

    // x0h (fp16 copy of inputs for gathering)
    cvt0_kernel<<<n4_blocks, TB>>>(user_w, item_w);

    // layers 1,2 into fp16 buffers; layer 3 fused with the final mean
    pull_kernel<false><<<pw_blocks, TB>>>(0, 1, user_w, item_w, out);
    pull_kernel<false><<<pw_blocks, TB>>>(1, 2, user_w, item_w, out);
    pull_kernel<true ><<<pw_blocks, TB>>>(2, 0, user_w, item_w, out);
}

// round 9
// speedup vs baseline: 1.1723x; 1.1723x over previous
#include <cuda_runtime.h>
#include <cuda_fp16.h>

// LightGCN pull-form: out = 0.25*(x0+x1+x2+x3), x_{l+1}[c] = sum_{e: col[e]=c} norm_e * x_l[row[e]]
// norm_e = rsqrt(deg[row])*rsqrt(deg[col]); deg = in-degree over col (symmetric list).
// edge_index int32. CSR (src-only) rebuilt every call; fp16 feature storage, fp32 math.
// Pull: one warp per dst node, HALF-warp per edge (R6 structure), final mean fused into pull 3.

static constexpr int    NU = 100000;
static constexpr int    NI = 50000;
static constexpr int    NN = NU + NI;        // 150000
static constexpr int    D  = 128;
static constexpr int    NE = 2000000;
static constexpr size_t ND = (size_t)NN * D; // 19.2M elems

static constexpr int SCAN_B   = 1024;
static constexpr int NSCANBLK = (NN + SCAN_B - 1) / SCAN_B;  // 147
static_assert(NSCANBLK <= 256, "scan2 single block assumption");

// ---- static scratch ----
__device__ __half g_xh[3][ND];    // x0h, x1h, x2h fp16 features (38.4 MB each)
__device__ float  g_dinv[NN];
__device__ int    g_deg[NN];
__device__ int    g_rowptr[NN + 1];
__device__ int    g_cursor[NN];
__device__ int    g_bsum[256];
__device__ int    g_edge[NE];     // src only, grouped by dst

// ---- helpers ----
__device__ __forceinline__ float4 h4_to_f4(uint2 v) {
    float2 f0 = __half22float2(*reinterpret_cast<__half2*>(&v.x));
    float2 f1 = __half22float2(*reinterpret_cast<__half2*>(&v.y));
    return make_float4(f0.x, f0.y, f1.x, f1.y);
}
__device__ __forceinline__ uint2 f4_to_h4(float4 v) {
    __half2 h0 = __floats2half2_rn(v.x, v.y);
    __half2 h1 = __floats2half2_rn(v.z, v.w);
    uint2 o;
    o.x = *reinterpret_cast<unsigned*>(&h0);
    o.y = *reinterpret_cast<unsigned*>(&h1);
    return o;
}

// ---------------- degree ----------------
__global__ void deg_kernel(const int* __restrict__ col, int E) {
    int e = blockIdx.x * blockDim.x + threadIdx.x;
    if (e < E) {
        unsigned c = (unsigned)col[e];
        if (c < (unsigned)NN) atomicAdd(&g_deg[c], 1);
    }
}

// ---------------- scan part 1 (+ fused dinv) ----------------
__global__ void scan1_kernel() {
    __shared__ int s[SCAN_B];
    int tid = threadIdx.x;
    int i = blockIdx.x * SCAN_B + tid;
    int v = (i < NN) ? g_deg[i] : 0;
    if (i < NN) g_dinv[i] = (v > 0) ? rsqrtf((float)v) : 0.0f;
    s[tid] = v;
    __syncthreads();
    for (int off = 1; off < SCAN_B; off <<= 1) {
        int t = (tid >= off) ? s[tid - off] : 0;
        __syncthreads();
        s[tid] += t;
        __syncthreads();
    }
    if (i < NN) g_rowptr[i] = s[tid] - v;
    if (tid == SCAN_B - 1) g_bsum[blockIdx.x] = s[tid];
}

__global__ void scan2_kernel() {
    __shared__ int s[256];
    int tid = threadIdx.x;
    int v = (tid < NSCANBLK) ? g_bsum[tid] : 0;
    s[tid] = v;
    __syncthreads();
    for (int off = 1; off < 256; off <<= 1) {
        int t = (tid >= off) ? s[tid - off] : 0;
        __syncthreads();
        s[tid] += t;
        __syncthreads();
    }
    g_bsum[tid] = s[tid] - v;
}

__global__ void scan3_kernel(int E) {
    int i = blockIdx.x * blockDim.x + threadIdx.x;
    if (i < NN) {
        int rp = g_rowptr[i] + g_bsum[i / SCAN_B];
        g_rowptr[i] = rp;
        g_cursor[i] = rp;
    }
    if (i == 0) g_rowptr[NN] = E;
}

// ---------------- CSR fill (src only) ----------------
__global__ void fill_kernel(const int* __restrict__ row,
                            const int* __restrict__ col, int E) {
    int e = blockIdx.x * blockDim.x + threadIdx.x;
    if (e < E) {
        unsigned r = (unsigned)row[e];
        unsigned c = (unsigned)col[e];
        if (r < (unsigned)NN && c < (unsigned)NN) {
            int pos = atomicAdd(&g_cursor[c], 1);
            g_edge[pos] = (int)r;
        }
    }
}

// ---------------- x0h = fp16(concat(user, item)) ----------------
__global__ void cvt0_kernel(const float* __restrict__ user_w,
                            const float* __restrict__ item_w) {
    size_t i = (size_t)blockIdx.x * blockDim.x + threadIdx.x; // float4 index
    const size_t n4  = ND / 4;
    const size_t nu4 = (size_t)NU * (D / 4);
    if (i < n4) {
        float4 v = (i < nu4) ? ((const float4*)user_w)[i]
                             : ((const float4*)item_w)[i - nu4];
        ((uint2*)g_xh[0])[i] = f4_to_h4(v);
    }
}

// ---------------- pull ----------------
// One warp per dst node; half-warp per edge; lane slice = 16 B (uint4 = 8 halves).
// half = lane>>4 (edge of the pair), sub = lane&15 (slice within 256B row).
// After xor-16 reduction both halves hold the full sums; lane (half,sub) writes
// granule sub*2+half (4 floats / 4 halves) -> all 32 lanes store, coalesced.
// FINAL: emit out = 0.25*(x0_fp32 + x1h + x2h + x3_fp32) instead of storing x3h.
template <bool FINAL>
__global__ void __launch_bounds__(256) pull_kernel(
    int lin, int lout,
    const float* __restrict__ user_w, const float* __restrict__ item_w,
    float* __restrict__ out)
{
    int node = (int)((blockIdx.x * (size_t)blockDim.x + threadIdx.x) >> 5);
    int lane = threadIdx.x & 31;
    if (node >= NN) return;

    int beg = g_rowptr[node];
    int end = g_rowptr[node + 1];
    float dn = g_dinv[node];

    int half = lane >> 4;   // which edge of the pair
    int sub  = lane & 15;   // 16B slice within the 256B row

    const uint4* __restrict__ xin = (const uint4*)g_xh[lin]; // 16 uint4 per row

    float a0 = 0.f, a1 = 0.f, a2 = 0.f, a3 = 0.f;
    float a4 = 0.f, a5 = 0.f, a6 = 0.f, a7 = 0.f;

    #pragma unroll 2
    for (int j = beg; j < end; j += 2) {
        int jj = j + half;
        float nrm = 0.f;
        uint4 r = make_uint4(0u, 0u, 0u, 0u);
        if (jj < end) {
            int src = g_edge[jj];
            nrm = g_dinv[src] * dn;
            r = xin[(size_t)src * 16 + sub];
        }
        float2 f0 = __half22float2(*reinterpret_cast<__half2*>(&r.x));
        float2 f1 = __half22float2(*reinterpret_cast<__half2*>(&r.y));
        float2 f2 = __half22float2(*reinterpret_cast<__half2*>(&r.z));
        float2 f3 = __half22float2(*reinterpret_cast<__half2*>(&r.w));
        a0 = fmaf(nrm, f0.x, a0); a1 = fmaf(nrm, f0.y, a1);
        a2 = fmaf(nrm, f1.x, a2); a3 = fmaf(nrm, f1.y, a3);
        a4 = fmaf(nrm, f2.x, a4); a5 = fmaf(nrm, f2.y, a5);
        a6 = fmaf(nrm, f3.x, a6); a7 = fmaf(nrm, f3.y, a7);
    }

    // combine the two half-warps (lane L and L+16 hold the same feature slice)
    a0 += __shfl_xor_sync(0xFFFFFFFFu, a0, 16);
    a1 += __shfl_xor_sync(0xFFFFFFFFu, a1, 16);
    a2 += __shfl_xor_sync(0xFFFFFFFFu, a2, 16);
    a3 += __shfl_xor_sync(0xFFFFFFFFu, a3, 16);
    a4 += __shfl_xor_sync(0xFFFFFFFFu, a4, 16);
    a5 += __shfl_xor_sync(0xFFFFFFFFu, a5, 16);
    a6 += __shfl_xor_sync(0xFFFFFFFFu, a6, 16);
    a7 += __shfl_xor_sync(0xFFFFFFFFu, a7, 16);

    // lane (half, sub) owns 4-elem granule sub*2 + half
    float b0 = half ? a4 : a0;
    float b1 = half ? a5 : a1;
    float b2 = half ? a6 : a2;
    float b3 = half ? a7 : a3;
    size_t idx = (size_t)node * 32 + sub * 2 + half;   // float4 / uint2 granule

    if (FINAL) {
        float4 x0 = (node < NU)
            ? ((const float4*)user_w)[idx]
            : ((const float4*)item_w)[idx - (size_t)NU * 32];
        float4 x1 = h4_to_f4(((const uint2*)g_xh[1])[idx]);
        float4 x2 = h4_to_f4(((const uint2*)g_xh[2])[idx]);
        float4 o;
        o.x = 0.25f * (x0.x + x1.x + x2.x + b0);
        o.y = 0.25f * (x0.y + x1.y + x2.y + b1);
        o.z = 0.25f * (x0.z + x1.z + x2.z + b2);
        o.w = 0.25f * (x0.w + x1.w + x2.w + b3);
        ((float4*)out)[idx] = o;
    } else {
        ((uint2*)g_xh[lout])[idx] = f4_to_h4(make_float4(b0, b1, b2, b3));
    }
}

extern "C" void kernel_launch(void* const* d_in, const int* in_sizes, int n_in,
                              void* d_out, int out_size)
{
    const int*   edge_index = (const int*)d_in[0];   // [2, E] int32
    const float* user_w     = (const float*)d_in[1]; // [NU, D]
    const float* item_w     = (const float*)d_in[2]; // [NI, D]
    float*       out        = (float*)d_out;         // [NN, D]

    const int E = in_sizes[0] / 2;
    const int* row = edge_index;
    const int* col = edge_index + E;

    const int TB = 256;
    const int n4_blocks = (int)((ND / 4 + TB - 1) / TB);
    const int nn_blocks = (NN + TB - 1) / TB;
    const int e_blocks  = (E + TB - 1) / TB;
    const int pw_blocks = (NN + (TB / 32) - 1) / (TB / 32);

    // zero degree via captured memset
    void* deg_ptr = nullptr;
    cudaGetSymbolAddress(&deg_ptr, g_deg);
    cudaMemsetAsync(deg_ptr, 0, NN * sizeof(int));

    // degree -> (scan + dinv) -> rowptr -> fill
    deg_kernel<<<e_blocks, TB>>>(col, E);
    scan1_kernel<<<NSCANBLK, SCAN_B>>>();
    scan2_kernel<<<1, 256>>>();
    scan3_kernel<<<nn_blocks, TB>>>(E);
    fill_kernel<<<e_blocks, TB>>>(row, col, E);

    // x0h (fp16 copy of inputs for gathering)
    cvt0_kernel<<<n4_blocks, TB>>>(user_w, item_w);

    // layers 1,2 into fp16 buffers; layer 3 fused with the final mean
    pull_kernel<false><<<pw_blocks, TB>>>(0, 1, user_w, item_w, out);
    pull_kernel<false><<<pw_blocks, TB>>>(1, 2, user_w, item_w, out);
    pull_kernel<true ><<<pw_blocks, TB>>>(2, 0, user_w, item_w, out);
}

// round 10
// speedup vs baseline: 1.2262x; 1.0460x over previous
#include <cuda_runtime.h>
#include <cuda_fp16.h>

// LightGCN pull-form with dinv folded into storage:
//   z_l := dinv ⊙ x_l   (fp16 storage)
//   pull:  t[c] = sum_{e: col=c} z_l[row_e]        (pure sum, no per-edge weights)
//   x_{l+1}[c] = dinv[c] * t ;  z_{l+1}[c] = dinv[c]^2 * t
//   out = 0.25*(x0 + sqd*z1 + sqd*z2 + dinv*t3),  sqd = sqrt(deg) (0 if deg=0)
// edge_index int32. CSR (src-only) rebuilt every call; fp32 accumulation.
// Pull: one warp per dst node, half-warp per edge, 16B lane slices, unroll 4.

static constexpr int    NU = 100000;
static constexpr int    NI = 50000;
static constexpr int    NN = NU + NI;        // 150000
static constexpr int    D  = 128;
static constexpr int    NE = 2000000;
static constexpr size_t ND = (size_t)NN * D; // 19.2M elems

static constexpr int SCAN_B   = 1024;
static constexpr int NSCANBLK = (NN + SCAN_B - 1) / SCAN_B;  // 147
static_assert(NSCANBLK <= 256, "scan2 single block assumption");

// ---- static scratch ----
__device__ __half g_xh[3][ND];    // z0, z1, z2 fp16 (38.4 MB each)
__device__ float  g_dinv[NN];
__device__ float  g_sqd[NN];      // sqrt(deg), 0 if deg==0
__device__ int    g_deg[NN];
__device__ int    g_rowptr[NN + 1];
__device__ int    g_cursor[NN];
__device__ int    g_bsum[256];
__device__ int    g_edge[NE];     // src only, grouped by dst

// ---- helpers ----
__device__ __forceinline__ float4 h4_to_f4(uint2 v) {
    float2 f0 = __half22float2(*reinterpret_cast<__half2*>(&v.x));
    float2 f1 = __half22float2(*reinterpret_cast<__half2*>(&v.y));
    return make_float4(f0.x, f0.y, f1.x, f1.y);
}
__device__ __forceinline__ uint2 f4_to_h4(float4 v) {
    __half2 h0 = __floats2half2_rn(v.x, v.y);
    __half2 h1 = __floats2half2_rn(v.z, v.w);
    uint2 o;
    o.x = *reinterpret_cast<unsigned*>(&h0);
    o.y = *reinterpret_cast<unsigned*>(&h1);
    return o;
}

// ---------------- degree ----------------
__global__ void deg_kernel(const int* __restrict__ col, int E) {
    int e = blockIdx.x * blockDim.x + threadIdx.x;
    if (e < E) {
        unsigned c = (unsigned)col[e];
        if (c < (unsigned)NN) atomicAdd(&g_deg[c], 1);
    }
}

// ---------------- scan part 1 (+ fused dinv & sqrt(deg)) ----------------
__global__ void scan1_kernel() {
    __shared__ int s[SCAN_B];
    int tid = threadIdx.x;
    int i = blockIdx.x * SCAN_B + tid;
    int v = (i < NN) ? g_deg[i] : 0;
    if (i < NN) {
        g_dinv[i] = (v > 0) ? rsqrtf((float)v) : 0.0f;
        g_sqd[i]  = sqrtf((float)v);
    }
    s[tid] = v;
    __syncthreads();
    for (int off = 1; off < SCAN_B; off <<= 1) {
        int t = (tid >= off) ? s[tid - off] : 0;
        __syncthreads();
        s[tid] += t;
        __syncthreads();
    }
    if (i < NN) g_rowptr[i] = s[tid] - v;
    if (tid == SCAN_B - 1) g_bsum[blockIdx.x] = s[tid];
}

__global__ void scan2_kernel() {
    __shared__ int s[256];
    int tid = threadIdx.x;
    int v = (tid < NSCANBLK) ? g_bsum[tid] : 0;
    s[tid] = v;
    __syncthreads();
    for (int off = 1; off < 256; off <<= 1) {
        int t = (tid >= off) ? s[tid - off] : 0;
        __syncthreads();
        s[tid] += t;
        __syncthreads();
    }
    g_bsum[tid] = s[tid] - v;
}

__global__ void scan3_kernel(int E) {
    int i = blockIdx.x * blockDim.x + threadIdx.x;
    if (i < NN) {
        int rp = g_rowptr[i] + g_bsum[i / SCAN_B];
        g_rowptr[i] = rp;
        g_cursor[i] = rp;
    }
    if (i == 0) g_rowptr[NN] = E;
}

// ---------------- CSR fill (src only) ----------------
__global__ void fill_kernel(const int* __restrict__ row,
                            const int* __restrict__ col, int E) {
    int e = blockIdx.x * blockDim.x + threadIdx.x;
    if (e < E) {
        unsigned r = (unsigned)row[e];
        unsigned c = (unsigned)col[e];
        if (r < (unsigned)NN && c < (unsigned)NN) {
            int pos = atomicAdd(&g_cursor[c], 1);
            g_edge[pos] = (int)r;
        }
    }
}

// ---------------- z0 = fp16( dinv * concat(user, item) ) ----------------
__global__ void cvt0_kernel(const float* __restrict__ user_w,
                            const float* __restrict__ item_w) {
    size_t i = (size_t)blockIdx.x * blockDim.x + threadIdx.x; // float4 granule
    const size_t n4  = ND / 4;
    const size_t nu4 = (size_t)NU * (D / 4);
    if (i < n4) {
        float4 v = (i < nu4) ? ((const float4*)user_w)[i]
                             : ((const float4*)item_w)[i - nu4];
        float dn = g_dinv[i >> 5];   // 32 granules per node
        v.x *= dn; v.y *= dn; v.z *= dn; v.w *= dn;
        ((uint2*)g_xh[0])[i] = f4_to_h4(v);
    }
}

// ---------------- pull ----------------
// One warp per dst node; half-warp per edge; lane slice = 16 B (uint4 = 8 halves).
// t = sum of z[src] (no weights). Non-final stores z_out = dinv^2 * t.
// FINAL emits out = 0.25*(x0_fp32 + sqd*z1 + sqd*z2 + dinv*t).
template <bool FINAL>
__global__ void __launch_bounds__(256) pull_kernel(
    int lin, int lout,
    const float* __restrict__ user_w, const float* __restrict__ item_w,
    float* __restrict__ out)
{
    int node = (int)((blockIdx.x * (size_t)blockDim.x + threadIdx.x) >> 5);
    int lane = threadIdx.x & 31;
    if (node >= NN) return;

    int beg = g_rowptr[node];
    int end = g_rowptr[node + 1];

    int half = lane >> 4;   // which edge of the pair
    int sub  = lane & 15;   // 16B slice within the 256B row

    const uint4* __restrict__ xin = (const uint4*)g_xh[lin]; // 16 uint4 per row

    float a0 = 0.f, a1 = 0.f, a2 = 0.f, a3 = 0.f;
    float a4 = 0.f, a5 = 0.f, a6 = 0.f, a7 = 0.f;

    #pragma unroll 4
    for (int j = beg; j < end; j += 2) {
        int jj = j + half;
        uint4 r = make_uint4(0u, 0u, 0u, 0u);
        if (jj < end) {
            int src = g_edge[jj];
            r = xin[(size_t)src * 16 + sub];
        }
        float2 f0 = __half22float2(*reinterpret_cast<__half2*>(&r.x));
        float2 f1 = __half22float2(*reinterpret_cast<__half2*>(&r.y));
        float2 f2 = __half22float2(*reinterpret_cast<__half2*>(&r.z));
        float2 f3 = __half22float2(*reinterpret_cast<__half2*>(&r.w));
        a0 += f0.x; a1 += f0.y;
        a2 += f1.x; a3 += f1.y;
        a4 += f2.x; a5 += f2.y;
        a6 += f3.x; a7 += f3.y;
    }

    // combine the two half-warps (lane L and L+16 hold the same feature slice)
    a0 += __shfl_xor_sync(0xFFFFFFFFu, a0, 16);
    a1 += __shfl_xor_sync(0xFFFFFFFFu, a1, 16);
    a2 += __shfl_xor_sync(0xFFFFFFFFu, a2, 16);
    a3 += __shfl_xor_sync(0xFFFFFFFFu, a3, 16);
    a4 += __shfl_xor_sync(0xFFFFFFFFu, a4, 16);
    a5 += __shfl_xor_sync(0xFFFFFFFFu, a5, 16);
    a6 += __shfl_xor_sync(0xFFFFFFFFu, a6, 16);
    a7 += __shfl_xor_sync(0xFFFFFFFFu, a7, 16);

    // lane (half, sub) owns 4-elem granule sub*2 + half
    float b0 = half ? a4 : a0;
    float b1 = half ? a5 : a1;
    float b2 = half ? a6 : a2;
    float b3 = half ? a7 : a3;
    size_t idx = (size_t)node * 32 + sub * 2 + half;   // float4 / uint2 granule

    float dn = g_dinv[node];

    if (FINAL) {
        float sd = g_sqd[node];
        float4 x0 = (node < NU)
            ? ((const float4*)user_w)[idx]
            : ((const float4*)item_w)[idx - (size_t)NU * 32];
        float4 z1 = h4_to_f4(((const uint2*)g_xh[1])[idx]);
        float4 z2 = h4_to_f4(((const uint2*)g_xh[2])[idx]);
        float4 o;
        o.x = 0.25f * (x0.x + sd * (z1.x + z2.x) + dn * b0);
        o.y = 0.25f * (x0.y + sd * (z1.y + z2.y) + dn * b1);
        o.z = 0.25f * (x0.z + sd * (z1.z + z2.z) + dn * b2);
        o.w = 0.25f * (x0.w + sd * (z1.w + z2.w) + dn * b3);
        ((float4*)out)[idx] = o;
    } else {
        float s = dn * dn;   // z_out = dinv^2 * t
        ((uint2*)g_xh[lout])[idx] =
            f4_to_h4(make_float4(s * b0, s * b1, s * b2, s * b3));
    }
}

extern "C" void kernel_launch(void* const* d_in, const int* in_sizes, int n_in,
                              void* d_out, int out_size)
{
    const int*   edge_index = (const int*)d_in[0];   // [2, E] int32
    const float* user_w     = (const float*)d_in[1]; // [NU, D]
    const float* item_w     = (const float*)d_in[2]; // [NI, D]
    float*       out        = (float*)d_out;         // [NN, D]

    const int E = in_sizes[0] / 2;
    const int* row = edge_index;
    const int* col = edge_index + E;

    const int TB = 256;
    const int n4_blocks = (int)((ND / 4 + TB - 1) / TB);
    const int nn_blocks = (NN + TB - 1) / TB;
    const int e_blocks  = (E + TB - 1) / TB;
    const int pw_blocks = (NN + (TB / 32) - 1) / (TB / 32);

    // zero degree via captured memset
    void* deg_ptr = nullptr;
    cudaGetSymbolAddress(&deg_ptr, g_deg);
    cudaMemsetAsync(deg_ptr, 0, NN * sizeof(int));

    // degree -> (scan + dinv + sqd) -> rowptr -> fill
    deg_kernel<<<e_blocks, TB>>>(col, E);
    scan1_kernel<<<NSCANBLK, SCAN_B>>>();
    scan2_kernel<<<1, 256>>>();
    scan3_kernel<<<nn_blocks, TB>>>(E);
    fill_kernel<<<e_blocks, TB>>>(row, col, E);

    // z0 = dinv * x0 in fp16 (needs dinv from scan1)
    cvt0_kernel<<<n4_blocks, TB>>>(user_w, item_w);

    // layers 1,2 into fp16 z-buffers; layer 3 fused with the final mean
    pull_kernel<false><<<pw_blocks, TB>>>(0, 1, user_w, item_w, out);
    pull_kernel<false><<<pw_blocks, TB>>>(1, 2, user_w, item_w, out);
    pull_kernel<true ><<<pw_blocks, TB>>>(2, 0, user_w, item_w, out);
}

// round 11
// speedup vs baseline: 1.2747x; 1.0395x over previous
#include <cuda_runtime.h>
#include <cuda_fp16.h>

// LightGCN pull-form with dinv folded into storage:
//   z_l := dinv ⊙ x_l   (fp16 storage)
//   pull:  t[c] = sum_{e: col=c} z_l[row_e]        (pure sum, no per-edge weights)
//   z_{l+1}[c] = dinv[c]^2 * t ;  out = 0.25*(x0 + sqd*(z1+z2) + dinv*t3)
// edge_index int32. CSR (src-only) rebuilt every call; fp32 accumulation.
// CSR is PADDED to even per-node degree with dummy src = NN (feature row NN is
// permanently zero), so the pull inner loop is branch-free.

static constexpr int    NU = 100000;
static constexpr int    NI = 50000;
static constexpr int    NN = NU + NI;        // 150000
static constexpr int    D  = 128;
static constexpr int    NE = 2000000;
static constexpr size_t ND = (size_t)NN * D; // 19.2M elems

static constexpr int SCAN_B   = 1024;
static constexpr int NSCANBLK = (NN + SCAN_B - 1) / SCAN_B;  // 147
static_assert(NSCANBLK <= 256, "scan2 single block assumption");

// ---- static scratch ----
// One extra zero feature row (index NN) per buffer: .bss zero-init, never written.
__device__ __half g_xh[3][ND + D];  // z0, z1, z2 fp16
__device__ float  g_dinv[NN];
__device__ float  g_sqd[NN];        // sqrt(deg), 0 if deg==0
__device__ int    g_deg[NN];
__device__ int    g_rowptr[NN + 1]; // padded offsets
__device__ int    g_cursor[NN];
__device__ int    g_bsum[256];
__device__ int    g_edge[NE + NN];  // src only, grouped by dst, even-padded

// ---- helpers ----
__device__ __forceinline__ float4 h4_to_f4(uint2 v) {
    float2 f0 = __half22float2(*reinterpret_cast<__half2*>(&v.x));
    float2 f1 = __half22float2(*reinterpret_cast<__half2*>(&v.y));
    return make_float4(f0.x, f0.y, f1.x, f1.y);
}
__device__ __forceinline__ uint2 f4_to_h4(float4 v) {
    __half2 h0 = __floats2half2_rn(v.x, v.y);
    __half2 h1 = __floats2half2_rn(v.z, v.w);
    uint2 o;
    o.x = *reinterpret_cast<unsigned*>(&h0);
    o.y = *reinterpret_cast<unsigned*>(&h1);
    return o;
}

// ---------------- degree ----------------
__global__ void deg_kernel(const int* __restrict__ col, int E) {
    int e = blockIdx.x * blockDim.x + threadIdx.x;
    if (e < E) {
        unsigned c = (unsigned)col[e];
        if (c < (unsigned)NN) atomicAdd(&g_deg[c], 1);
    }
}

// ---------------- scan part 1 over PADDED degree (+ dinv & sqrt(deg)) ----------------
__global__ void scan1_kernel() {
    __shared__ int s[SCAN_B];
    int tid = threadIdx.x;
    int i = blockIdx.x * SCAN_B + tid;
    int d = (i < NN) ? g_deg[i] : 0;
    int v = (d + 1) & ~1;                      // padded degree
    if (i < NN) {
        g_dinv[i] = (d > 0) ? rsqrtf((float)d) : 0.0f;
        g_sqd[i]  = sqrtf((float)d);
    }
    s[tid] = v;
    __syncthreads();
    for (int off = 1; off < SCAN_B; off <<= 1) {
        int t = (tid >= off) ? s[tid - off] : 0;
        __syncthreads();
        s[tid] += t;
        __syncthreads();
    }
    if (i < NN) g_rowptr[i] = s[tid] - v;
    if (tid == SCAN_B - 1) g_bsum[blockIdx.x] = s[tid];
}

__global__ void scan2_kernel() {
    __shared__ int s[256];
    int tid = threadIdx.x;
    int v = (tid < NSCANBLK) ? g_bsum[tid] : 0;
    s[tid] = v;
    __syncthreads();
    for (int off = 1; off < 256; off <<= 1) {
        int t = (tid >= off) ? s[tid - off] : 0;
        __syncthreads();
        s[tid] += t;
        __syncthreads();
    }
    g_bsum[tid] = s[tid] - v;
}

// finalize rowptr, init cursor, write pad slots (dummy src = NN)
__global__ void scan3_kernel() {
    int i = blockIdx.x * blockDim.x + threadIdx.x;
    if (i < NN) {
        int rp = g_rowptr[i] + g_bsum[i / SCAN_B];
        g_rowptr[i] = rp;
        g_cursor[i] = rp;
        int d = g_deg[i];
        if (d & 1) g_edge[rp + d] = NN;        // single pad slot
        if (i == NN - 1) g_rowptr[NN] = rp + ((d + 1) & ~1);
    }
}

// ---------------- CSR fill (src only) ----------------
__global__ void fill_kernel(const int* __restrict__ row,
                            const int* __restrict__ col, int E) {
    int e = blockIdx.x * blockDim.x + threadIdx.x;
    if (e < E) {
        unsigned r = (unsigned)row[e];
        unsigned c = (unsigned)col[e];
        if (r < (unsigned)NN && c < (unsigned)NN) {
            int pos = atomicAdd(&g_cursor[c], 1);
            g_edge[pos] = (int)r;
        }
    }
}

// ---------------- z0 = fp16( dinv * concat(user, item) ) ----------------
__global__ void cvt0_kernel(const float* __restrict__ user_w,
                            const float* __restrict__ item_w) {
    size_t i = (size_t)blockIdx.x * blockDim.x + threadIdx.x; // float4 granule
    const size_t n4  = ND / 4;
    const size_t nu4 = (size_t)NU * (D / 4);
    if (i < n4) {
        float4 v = (i < nu4) ? ((const float4*)user_w)[i]
                             : ((const float4*)item_w)[i - nu4];
        float dn = g_dinv[i >> 5];   // 32 granules per node
        v.x *= dn; v.y *= dn; v.z *= dn; v.w *= dn;
        ((uint2*)g_xh[0])[i] = f4_to_h4(v);
    }
}

// ---------------- pull ----------------
// One warp per dst node; half-warp per edge; lane slice = 16 B (uint4 = 8 halves).
// Edge list is even-padded -> branch-free inner loop (dummy src NN is a zero row).
// Non-final stores z_out = dinv^2 * t. FINAL emits out = 0.25*(x0 + sqd*(z1+z2) + dinv*t).
template <bool FINAL>
__global__ void __launch_bounds__(256) pull_kernel(
    int lin, int lout,
    const float* __restrict__ user_w, const float* __restrict__ item_w,
    float* __restrict__ out)
{
    int node = (int)((blockIdx.x * (size_t)blockDim.x + threadIdx.x) >> 5);
    int lane = threadIdx.x & 31;
    if (node >= NN) return;

    int beg = g_rowptr[node];
    int end = g_rowptr[node + 1];

    int half = lane >> 4;   // which edge of the pair
    int sub  = lane & 15;   // 16B slice within the 256B row

    const uint4* __restrict__ xin = (const uint4*)g_xh[lin]; // 16 uint4 per row

    float a0 = 0.f, a1 = 0.f, a2 = 0.f, a3 = 0.f;
    float a4 = 0.f, a5 = 0.f, a6 = 0.f, a7 = 0.f;

    #pragma unroll 4
    for (int j = beg; j < end; j += 2) {
        int src = g_edge[j + half];
        uint4 r = xin[(size_t)src * 16 + sub];
        float2 f0 = __half22float2(*reinterpret_cast<__half2*>(&r.x));
        float2 f1 = __half22float2(*reinterpret_cast<__half2*>(&r.y));
        float2 f2 = __half22float2(*reinterpret_cast<__half2*>(&r.z));
        float2 f3 = __half22float2(*reinterpret_cast<__half2*>(&r.w));
        a0 += f0.x; a1 += f0.y;
        a2 += f1.x; a3 += f1.y;
        a4 += f2.x; a5 += f2.y;
        a6 += f3.x; a7 += f3.y;
    }

    // combine the two half-warps (lane L and L+16 hold the same feature slice)
    a0 += __shfl_xor_sync(0xFFFFFFFFu, a0, 16);
    a1 += __shfl_xor_sync(0xFFFFFFFFu, a1, 16);
    a2 += __shfl_xor_sync(0xFFFFFFFFu, a2, 16);
    a3 += __shfl_xor_sync(0xFFFFFFFFu, a3, 16);
    a4 += __shfl_xor_sync(0xFFFFFFFFu, a4, 16);
    a5 += __shfl_xor_sync(0xFFFFFFFFu, a5, 16);
    a6 += __shfl_xor_sync(0xFFFFFFFFu, a6, 16);
    a7 += __shfl_xor_sync(0xFFFFFFFFu, a7, 16);

    // lane (half, sub) owns 4-elem granule sub*2 + half
    float b0 = half ? a4 : a0;
    float b1 = half ? a5 : a1;
    float b2 = half ? a6 : a2;
    float b3 = half ? a7 : a3;
    size_t idx = (size_t)node * 32 + sub * 2 + half;   // float4 / uint2 granule

    float dn = g_dinv[node];

    if (FINAL) {
        float sd = g_sqd[node];
        float4 x0 = (node < NU)
            ? ((const float4*)user_w)[idx]
            : ((const float4*)item_w)[idx - (size_t)NU * 32];
        float4 z1 = h4_to_f4(((const uint2*)g_xh[1])[idx]);
        float4 z2 = h4_to_f4(((const uint2*)g_xh[2])[idx]);
        float4 o;
        o.x = 0.25f * (x0.x + sd * (z1.x + z2.x) + dn * b0);
        o.y = 0.25f * (x0.y + sd * (z1.y + z2.y) + dn * b1);
        o.z = 0.25f * (x0.z + sd * (z1.z + z2.z) + dn * b2);
        o.w = 0.25f * (x0.w + sd * (z1.w + z2.w) + dn * b3);
        ((float4*)out)[idx] = o;
    } else {
        float s = dn * dn;   // z_out = dinv^2 * t
        ((uint2*)g_xh[lout])[idx] =
            f4_to_h4(make_float4(s * b0, s * b1, s * b2, s * b3));
    }
}

extern "C" void kernel_launch(void* const* d_in, const int* in_sizes, int n_in,
                              void* d_out, int out_size)
{
    const int*   edge_index = (const int*)d_in[0];   // [2, E] int32
    const float* user_w     = (const float*)d_in[1]; // [NU, D]
    const float* item_w     = (const float*)d_in[2]; // [NI, D]
    float*       out        = (float*)d_out;         // [NN, D]

    const int E = in_sizes[0] / 2;
    const int* row = edge_index;
    const int* col = edge_index + E;

    const int TB = 256;
    const int n4_blocks = (int)((ND / 4 + TB - 1) / TB);
    const int nn_blocks = (NN + TB - 1) / TB;
    const int e_blocks  = (E + TB - 1) / TB;
    const int pw_blocks = (NN + (TB / 32) - 1) / (TB / 32);

    // zero degree via captured memset
    void* deg_ptr = nullptr;
    cudaGetSymbolAddress(&deg_ptr, g_deg);
    cudaMemsetAsync(deg_ptr, 0, NN * sizeof(int));

    // degree -> (scan + dinv + sqd) -> rowptr/pads -> fill
    deg_kernel<<<e_blocks, TB>>>(col, E);
    scan1_kernel<<<NSCANBLK, SCAN_B>>>();
    scan2_kernel<<<1, 256>>>();
    scan3_kernel<<<nn_blocks, TB>>>();
    fill_kernel<<<e_blocks, TB>>>(row, col, E);

    // z0 = dinv * x0 in fp16 (needs dinv from scan1)
    cvt0_kernel<<<n4_blocks, TB>>>(user_w, item_w);

    // layers 1,2 into fp16 z-buffers; layer 3 fused with the final mean
    pull_kernel<false><<<pw_blocks, TB>>>(0, 1, user_w, item_w, out);
    pull_kernel<false><<<pw_blocks, TB>>>(1, 2, user_w, item_w, out);
    pull_kernel<true ><<<pw_blocks, TB>>>(2, 0, user_w, item_w, out);
}